// round 1
// baseline (speedup 1.0000x reference)
#include <cuda_runtime.h>
#include <cstdint>

// Problem constants
#define BATCH   16
#define CDIM    64          // EMBEDDING_DIM
#define HW      4096        // 64*64
#define KTOT    1024        // NUM_EMBEDDINGS
#define NTOT    (BATCH*HW)  // 65536 flat vectors
#define TM      128         // positions per block tile
#define TK      128         // codes per chunk
#define NCHUNK  (KTOT/TK)   // 8
#define NBLOCKS (NTOT/TM)   // 512
#define ELEMS   ((size_t)BATCH*CDIM*HW)   // 4194304

// Output layout: [loss(1)][quantized NCHW(4194304)][indices(65536)]
#define OUT_Q    1
#define OUT_IDX  (1 + (size_t)ELEMS)

// Scratch (device globals — no allocation allowed)
__device__ float g_eT[CDIM * KTOT];     // embedding transposed [c][k]
__device__ float g_enorm[KTOT];         // ||e_k||^2
__device__ float g_scratch[NBLOCKS];    // per-block loss partials

// ---------------- packed f32x2 helpers ----------------
__device__ __forceinline__ unsigned long long pack2(float a) {
    unsigned long long r;
    asm("mov.b64 %0, {%1, %1};" : "=l"(r) : "f"(a));
    return r;
}
__device__ __forceinline__ unsigned long long fma2(unsigned long long a,
                                                   unsigned long long b,
                                                   unsigned long long c) {
    unsigned long long d;
    asm("fma.rn.f32x2 %0, %1, %2, %3;" : "=l"(d) : "l"(a), "l"(b), "l"(c));
    return d;
}
__device__ __forceinline__ void unpack2(unsigned long long v, float& lo, float& hi) {
    asm("mov.b64 {%0, %1}, %2;" : "=f"(lo), "=f"(hi) : "l"(v));
}

// ---------------- prep: transpose embedding + code norms ----------------
// grid 64 x 256 threads. 16 threads per code row.
__global__ void vq_prep(const float* __restrict__ emb) {
    int t = threadIdx.x;
    int k = blockIdx.x * 16 + (t >> 4);
    int c = (t & 15) * 4;
    float4 v = *(const float4*)(emb + (size_t)k * CDIM + c);
    g_eT[(size_t)(c + 0) * KTOT + k] = v.x;
    g_eT[(size_t)(c + 1) * KTOT + k] = v.y;
    g_eT[(size_t)(c + 2) * KTOT + k] = v.z;
    g_eT[(size_t)(c + 3) * KTOT + k] = v.w;
    float p = v.x * v.x + v.y * v.y + v.z * v.z + v.w * v.w;
    p += __shfl_xor_sync(0xffffffffu, p, 1);
    p += __shfl_xor_sync(0xffffffffu, p, 2);
    p += __shfl_xor_sync(0xffffffffu, p, 4);
    p += __shfl_xor_sync(0xffffffffu, p, 8);
    if ((t & 15) == 0) g_enorm[k] = p;
}

// ---------------- main: distances + argmin + outputs ----------------
// One block = 128 positions (one batch image, 128 contiguous hw).
// 256 threads = 16(ty, j-dim) x 16(tx, k-dim); 8x8 register tile per thread.
// Dynamic smem: xs[64][128] | es[64][128] | en[128] | xn[128] | idx[128]
#define SMEM_BYTES (CDIM*TM*4 + CDIM*TK*4 + TM*4 + TM*4 + TM*4)

__global__ __launch_bounds__(256, 2)
void vq_main(const float* __restrict__ xin_all, float* __restrict__ out) {
    extern __shared__ float sm[];
    float* xs   = sm;                       // [64][128]  x tile, [c][j]
    float* es   = sm + CDIM * TM;           // [64][128]  e tile, [c][k]
    float* en_s = sm + 2 * CDIM * TM;       // [128] code norms (chunk)
    float* xn_s = en_s + TM;                // [128] ||x_j||^2, later loss partials
    int*   idx_s = (int*)(xn_s + TM);       // [128] winning indices
    // reduction overlays (xs no longer needed at that point)
    float* rs = xs;                         // [128][16] scores
    int*   ri = (int*)(xs + TM * 16);       // [128][16] indices

    const int tid = threadIdx.x;
    const int b   = blockIdx.x >> 5;        // 32 tiles per image
    const int hw0 = (blockIdx.x & 31) * TM;
    const float* xin = xin_all + (size_t)b * CDIM * HW + hw0;

    // Load X tile (NCHW is naturally [c][hw] -> coalesced, contiguous STS)
    #pragma unroll
    for (int p = 0; p < 8; p++) {
        int c = (tid >> 5) + p * 8;
        int j = (tid & 31) * 4;
        *(float4*)(xs + c * TM + j) = *(const float4*)(xin + (size_t)c * HW + j);
    }
    __syncthreads();

    // ||x_j||^2
    if (tid < TM) {
        float s = 0.f;
        #pragma unroll 8
        for (int c = 0; c < CDIM; c++) { float v = xs[c * TM + tid]; s += v * v; }
        xn_s[tid] = s;
    }

    const int ty = tid >> 4;   // j group
    const int tx = tid & 15;   // k group
    float best[8];
    int   bidx[8];
    #pragma unroll
    for (int jj = 0; jj < 8; jj++) { best[jj] = 3.4e38f; bidx[jj] = 0x7fffffff; }

    for (int chunk = 0; chunk < NCHUNK; chunk++) {
        const int kbase = chunk * TK;
        __syncthreads();   // previous compute done before es overwrite
        #pragma unroll
        for (int p = 0; p < 8; p++) {
            int c = (tid >> 5) + p * 8;
            int k = (tid & 31) * 4;
            *(float4*)(es + c * TK + k) =
                *(const float4*)(g_eT + (size_t)c * KTOT + kbase + k);
        }
        if (tid < TK) en_s[tid] = g_enorm[kbase + tid];
        __syncthreads();

        unsigned long long acc[8][4];
        #pragma unroll
        for (int jj = 0; jj < 8; jj++)
            #pragma unroll
            for (int kp = 0; kp < 4; kp++) acc[jj][kp] = 0ull;

        #pragma unroll 8
        for (int c = 0; c < CDIM; c++) {
            float4 xa = *(const float4*)(xs + c * TM + ty * 8);
            float4 xb = *(const float4*)(xs + c * TM + ty * 8 + 4);
            const unsigned long long* ep =
                (const unsigned long long*)(es + c * TK + tx * 8);
            unsigned long long e0 = ep[0], e1 = ep[1], e2 = ep[2], e3 = ep[3];
            float xv[8] = {xa.x, xa.y, xa.z, xa.w, xb.x, xb.y, xb.z, xb.w};
            #pragma unroll
            for (int jj = 0; jj < 8; jj++) {
                unsigned long long xx = pack2(xv[jj]);
                acc[jj][0] = fma2(xx, e0, acc[jj][0]);
                acc[jj][1] = fma2(xx, e1, acc[jj][1]);
                acc[jj][2] = fma2(xx, e2, acc[jj][2]);
                acc[jj][3] = fma2(xx, e3, acc[jj][3]);
            }
        }

        // scores: ||e||^2 - 2 x.e ; ascending-k order => strict < keeps first index
        const int klocal = tx * 8;
        #pragma unroll
        for (int jj = 0; jj < 8; jj++) {
            #pragma unroll
            for (int kp = 0; kp < 4; kp++) {
                float lo, hi;
                unpack2(acc[jj][kp], lo, hi);
                float s0 = en_s[klocal + 2 * kp]     - (lo + lo);
                float s1 = en_s[klocal + 2 * kp + 1] - (hi + hi);
                int k0 = kbase + klocal + 2 * kp;
                if (s0 < best[jj]) { best[jj] = s0; bidx[jj] = k0; }
                if (s1 < best[jj]) { best[jj] = s1; bidx[jj] = k0 + 1; }
            }
        }
    }

    __syncthreads();   // done reading xs; safe to overlay rs/ri
    #pragma unroll
    for (int jj = 0; jj < 8; jj++) {
        int j = ty * 8 + jj;
        rs[j * 16 + tx] = best[jj];
        ri[j * 16 + tx] = bidx[jj];
    }
    __syncthreads();

    if (tid < TM) {
        float bs = rs[tid * 16];
        int   bk = ri[tid * 16];
        #pragma unroll
        for (int t = 1; t < 16; t++) {
            float s = rs[tid * 16 + t];
            int   k = ri[tid * 16 + t];
            if (s < bs || (s == bs && k < bk)) { bs = s; bk = k; }
        }
        idx_s[tid] = bk;
        // indices output (float-encoded)
        out[OUT_IDX + (size_t)b * HW + hw0 + tid] = (float)bk;
        // loss partial: dist = score + ||x||^2
        xn_s[tid] = bs + xn_s[tid];
    }
    __syncthreads();

    // block loss reduction (deterministic)
    if (tid < 64) xn_s[tid] += xn_s[tid + 64];
    __syncthreads();
    if (tid < 32) {
        float v = xn_s[tid] + xn_s[tid + 32];
        v += __shfl_xor_sync(0xffffffffu, v, 16);
        v += __shfl_xor_sync(0xffffffffu, v, 8);
        v += __shfl_xor_sync(0xffffffffu, v, 4);
        v += __shfl_xor_sync(0xffffffffu, v, 2);
        v += __shfl_xor_sync(0xffffffffu, v, 1);
        if (tid == 0) g_scratch[blockIdx.x] = v;
    }

    // quantized output: out_q[b][c][hw0+j] = eT[c][idx_j]  (gathers hit L2; eT=256KB)
    const int j = tid & 127;
    const int myidx = idx_s[j];
    float* qout = out + OUT_Q + (size_t)b * CDIM * HW + hw0 + j;
    #pragma unroll 8
    for (int c = (tid >> 7); c < CDIM; c += 2) {
        qout[(size_t)c * HW] = g_eT[(size_t)c * KTOT + myidx];
    }
}

// ---------------- final loss ----------------
__global__ void vq_loss_final(float* __restrict__ out) {
    __shared__ float smw[16];
    int tid = threadIdx.x;       // 512 threads = NBLOCKS
    float v = g_scratch[tid];
    v += __shfl_xor_sync(0xffffffffu, v, 16);
    v += __shfl_xor_sync(0xffffffffu, v, 8);
    v += __shfl_xor_sync(0xffffffffu, v, 4);
    v += __shfl_xor_sync(0xffffffffu, v, 2);
    v += __shfl_xor_sync(0xffffffffu, v, 1);
    if ((tid & 31) == 0) smw[tid >> 5] = v;
    __syncthreads();
    if (tid < 16) {
        float s = smw[tid];
        s += __shfl_xor_sync(0xffffu, s, 8);
        s += __shfl_xor_sync(0xffffu, s, 4);
        s += __shfl_xor_sync(0xffffu, s, 2);
        s += __shfl_xor_sync(0xffffu, s, 1);
        if (tid == 0) out[0] = 0.25f * s / (float)ELEMS;
    }
}

extern "C" void kernel_launch(void* const* d_in, const int* in_sizes, int n_in,
                              void* d_out, int out_size) {
    const float* x   = (const float*)d_in[0];   // [16,64,64,64] NCHW
    const float* emb = (const float*)d_in[1];   // [1024,64]
    float* out = (float*)d_out;

    cudaFuncSetAttribute(vq_main, cudaFuncAttributeMaxDynamicSharedMemorySize,
                         SMEM_BYTES);

    vq_prep<<<KTOT / 16, 256>>>(emb);
    vq_main<<<NBLOCKS, 256, SMEM_BYTES>>>(x, out);
    vq_loss_final<<<1, NBLOCKS>>>(out);
}

// round 3
// speedup vs baseline: 1.3286x; 1.3286x over previous
#include <cuda_runtime.h>
#include <cstdint>

// Problem constants
#define BATCH   16
#define CDIM    64          // EMBEDDING_DIM
#define HW      4096        // 64*64
#define KTOT    1024        // NUM_EMBEDDINGS
#define NTOT    (BATCH*HW)  // 65536 flat vectors
#define TM      128         // positions per block tile
#define TK      128         // codes per chunk
#define NCHUNK  (KTOT/TK)   // 8
#define NBLOCKS (NTOT/TM)   // 512
#define ELEMS   ((size_t)BATCH*CDIM*HW)   // 4194304

// Output layout: [loss(1)][quantized NCHW(4194304)][indices(65536)]
#define OUT_Q    1
#define OUT_IDX  (1 + (size_t)ELEMS)

typedef unsigned long long u64;

// Scratch (device globals — no allocation allowed)
__device__ float g_eT[CDIM * KTOT];     // embedding transposed [c][k]
__device__ float g_enorm[KTOT];         // ||e_k||^2
__device__ float g_scratch[NBLOCKS];    // per-block loss partials

// ---------------- packed f32x2 helpers ----------------
__device__ __forceinline__ u64 fma2(u64 a, u64 b, u64 c) {
    u64 d;
    asm("fma.rn.f32x2 %0, %1, %2, %3;" : "=l"(d) : "l"(a), "l"(b), "l"(c));
    return d;
}
__device__ __forceinline__ void unpack2(u64 v, float& lo, float& hi) {
    asm("mov.b64 {%0, %1}, %2;" : "=f"(lo), "=f"(hi) : "l"(v));
}

// ---------------- prep: transpose embedding + code norms ----------------
__global__ void vq_prep(const float* __restrict__ emb) {
    int t = threadIdx.x;
    int k = blockIdx.x * 16 + (t >> 4);
    int c = (t & 15) * 4;
    float4 v = *(const float4*)(emb + (size_t)k * CDIM + c);
    g_eT[(size_t)(c + 0) * KTOT + k] = v.x;
    g_eT[(size_t)(c + 1) * KTOT + k] = v.y;
    g_eT[(size_t)(c + 2) * KTOT + k] = v.z;
    g_eT[(size_t)(c + 3) * KTOT + k] = v.w;
    float p = v.x * v.x + v.y * v.y + v.z * v.z + v.w * v.w;
    p += __shfl_xor_sync(0xffffffffu, p, 1);
    p += __shfl_xor_sync(0xffffffffu, p, 2);
    p += __shfl_xor_sync(0xffffffffu, p, 4);
    p += __shfl_xor_sync(0xffffffffu, p, 8);
    if ((t & 15) == 0) g_enorm[k] = p;
}

// ---------------- main: distances + argmin + outputs ----------------
// One block = 128 positions. 256 threads = 16(ty: j) x 16(tx: k); 8x8 tile/thread.
// Thread's k set: {2*tx + 32*m, 2*tx+1 + 32*m}, m=0..3  (conflict-free LDS.64)
// smem: xs2[64][128] float2 (x duplicated) | es[64][128] | en[128] | xn[128] | idx[128]
#define SMEM_BYTES (CDIM*TM*8 + CDIM*TK*4 + TM*4 + TM*4 + TM*4)

__global__ __launch_bounds__(256, 2)
void vq_main(const float* __restrict__ xin_all, const float* __restrict__ emb,
             float* __restrict__ out) {
    extern __shared__ float sm[];
    float* xs2  = sm;                         // [64][128] float2 dup  (64KB)
    float* es   = sm + CDIM * TM * 2;         // [64][128]             (32KB)
    float* en_s = es + CDIM * TK;             // [128]
    float* xn_s = en_s + TM;                  // [128]
    int*   idx_s = (int*)(xn_s + TM);         // [128]
    // overlays
    float* rs = xs2;                          // [128][16] scores (on xs2)
    int*   ri = (int*)(xs2 + TM * 16);        // [128][16] indices
    float* qs = es;                           // [64][128] quantized tile (on es)

    const int tid = threadIdx.x;
    const int b   = blockIdx.x >> 5;
    const int hw0 = (blockIdx.x & 31) * TM;
    const float* xin = xin_all + (size_t)b * CDIM * HW + hw0;

    // Load X tile, duplicated pairs (x,x) -> xs2
    #pragma unroll
    for (int p = 0; p < 8; p++) {
        int c = (tid >> 5) + p * 8;
        int j = (tid & 31) * 4;
        float4 v = *(const float4*)(xin + (size_t)c * HW + j);
        float4* d = (float4*)(xs2 + 2 * (c * TM + j));
        d[0] = make_float4(v.x, v.x, v.y, v.y);
        d[1] = make_float4(v.z, v.z, v.w, v.w);
    }
    __syncthreads();

    // ||x_j||^2
    if (tid < TM) {
        float s = 0.f;
        #pragma unroll 8
        for (int c = 0; c < CDIM; c++) { float v = xs2[2 * (c * TM + tid)]; s += v * v; }
        xn_s[tid] = s;
    }

    const int ty = tid >> 4;   // j group
    const int tx = tid & 15;   // k group
    float best[8];
    int   bidx[8];
    #pragma unroll
    for (int jj = 0; jj < 8; jj++) { best[jj] = 3.4e38f; bidx[jj] = 0x7fffffff; }

    for (int chunk = 0; chunk < NCHUNK; chunk++) {
        const int kbase = chunk * TK;
        __syncthreads();
        #pragma unroll
        for (int p = 0; p < 8; p++) {
            int c = (tid >> 5) + p * 8;
            int k = (tid & 31) * 4;
            *(float4*)(es + c * TK + k) =
                *(const float4*)(g_eT + (size_t)c * KTOT + kbase + k);
        }
        if (tid < TK) en_s[tid] = g_enorm[kbase + tid];
        __syncthreads();

        u64 acc[8][4];
        #pragma unroll
        for (int jj = 0; jj < 8; jj++)
            #pragma unroll
            for (int m = 0; m < 4; m++) acc[jj][m] = 0ull;

        #pragma unroll 4
        for (int c = 0; c < CDIM; c++) {
            const ulonglong2* xp = (const ulonglong2*)(xs2 + 2 * (c * TM + ty * 8));
            ulonglong2 xv0 = xp[0], xv1 = xp[1], xv2 = xp[2], xv3 = xp[3];
            const float* er = es + c * TK + 2 * tx;
            u64 e0 = *(const u64*)(er);
            u64 e1 = *(const u64*)(er + 32);
            u64 e2 = *(const u64*)(er + 64);
            u64 e3 = *(const u64*)(er + 96);
            u64 xj[8] = {xv0.x, xv0.y, xv1.x, xv1.y, xv2.x, xv2.y, xv3.x, xv3.y};
            #pragma unroll
            for (int jj = 0; jj < 8; jj++) {
                acc[jj][0] = fma2(xj[jj], e0, acc[jj][0]);
                acc[jj][1] = fma2(xj[jj], e1, acc[jj][1]);
                acc[jj][2] = fma2(xj[jj], e2, acc[jj][2]);
                acc[jj][3] = fma2(xj[jj], e3, acc[jj][3]);
            }
        }

        // scores: ||e||^2 - 2 x.e ; k ascending (m outer) => strict < keeps first
        #pragma unroll
        for (int m = 0; m < 4; m++) {
            const int k0 = kbase + 2 * tx + 32 * m;
            float2 en2 = *(const float2*)(en_s + 2 * tx + 32 * m);
            #pragma unroll
            for (int jj = 0; jj < 8; jj++) {
                float lo, hi;
                unpack2(acc[jj][m], lo, hi);
                float s0 = en2.x - (lo + lo);
                float s1 = en2.y - (hi + hi);
                if (s0 < best[jj]) { best[jj] = s0; bidx[jj] = k0; }
                if (s1 < best[jj]) { best[jj] = s1; bidx[jj] = k0 + 1; }
            }
        }
    }

    __syncthreads();   // done with xs2/es reads; overlays safe
    #pragma unroll
    for (int jj = 0; jj < 8; jj++) {
        int j = ty * 8 + jj;
        rs[j * 16 + tx] = best[jj];
        ri[j * 16 + tx] = bidx[jj];
    }
    __syncthreads();

    if (tid < TM) {
        float bs = rs[tid * 16];
        int   bk = ri[tid * 16];
        #pragma unroll
        for (int t = 1; t < 16; t++) {
            float s = rs[tid * 16 + t];
            int   k = ri[tid * 16 + t];
            if (s < bs || (s == bs && k < bk)) { bs = s; bk = k; }
        }
        idx_s[tid] = bk;
        out[OUT_IDX + (size_t)b * HW + hw0 + tid] = (float)bk;
        xn_s[tid] = bs + xn_s[tid];   // dist = score + ||x||^2
    }
    __syncthreads();

    // Gather emb rows (contiguous 256B each) into qs, transposed to [c][j]
    {
        const int jq = tid >> 1;
        const int c0 = (tid & 1) * 32;
        const int kq = idx_s[jq];
        const float4* erow = (const float4*)(emb + (size_t)kq * CDIM + c0);
        #pragma unroll
        for (int q = 0; q < 8; q++) {
            float4 v = erow[q];
            int c = c0 + q * 4;
            qs[(c + 0) * TM + jq] = v.x;
            qs[(c + 1) * TM + jq] = v.y;
            qs[(c + 2) * TM + jq] = v.z;
            qs[(c + 3) * TM + jq] = v.w;
        }
    }
    if (tid < 64) xn_s[tid] += xn_s[tid + 64];
    __syncthreads();

    if (tid < 32) {
        float v = xn_s[tid] + xn_s[tid + 32];
        v += __shfl_xor_sync(0xffffffffu, v, 16);
        v += __shfl_xor_sync(0xffffffffu, v, 8);
        v += __shfl_xor_sync(0xffffffffu, v, 4);
        v += __shfl_xor_sync(0xffffffffu, v, 2);
        v += __shfl_xor_sync(0xffffffffu, v, 1);
        if (tid == 0) g_scratch[blockIdx.x] = v;
    }

    // Coalesced quantized write — SCALAR stores (out+1 breaks 16B alignment;
    // float4/float2 stores here trap with misaligned address).
    {
        float* qbase = out + OUT_Q + (size_t)b * CDIM * HW + hw0;
        const int lane = tid & 31;
        #pragma unroll
        for (int p = 0; p < 8; p++) {
            int c = (tid >> 5) + p * 8;
            #pragma unroll
            for (int q = 0; q < 4; q++) {
                int j = lane + q * 32;
                qbase[(size_t)c * HW + j] = qs[c * TM + j];
            }
        }
    }
}

// ---------------- final loss ----------------
__global__ void vq_loss_final(float* __restrict__ out) {
    __shared__ float smw[16];
    int tid = threadIdx.x;       // 512 threads = NBLOCKS
    float v = g_scratch[tid];
    v += __shfl_xor_sync(0xffffffffu, v, 16);
    v += __shfl_xor_sync(0xffffffffu, v, 8);
    v += __shfl_xor_sync(0xffffffffu, v, 4);
    v += __shfl_xor_sync(0xffffffffu, v, 2);
    v += __shfl_xor_sync(0xffffffffu, v, 1);
    if ((tid & 31) == 0) smw[tid >> 5] = v;
    __syncthreads();
    if (tid < 16) {
        float s = smw[tid];
        s += __shfl_xor_sync(0xffffu, s, 8);
        s += __shfl_xor_sync(0xffffu, s, 4);
        s += __shfl_xor_sync(0xffffu, s, 2);
        s += __shfl_xor_sync(0xffffu, s, 1);
        if (tid == 0) out[0] = 0.25f * s / (float)ELEMS;
    }
}

extern "C" void kernel_launch(void* const* d_in, const int* in_sizes, int n_in,
                              void* d_out, int out_size) {
    const float* x   = (const float*)d_in[0];   // [16,64,64,64] NCHW
    const float* emb = (const float*)d_in[1];   // [1024,64]
    float* out = (float*)d_out;

    cudaFuncSetAttribute(vq_main, cudaFuncAttributeMaxDynamicSharedMemorySize,
                         SMEM_BYTES);

    vq_prep<<<KTOT / 16, 256>>>(emb);
    vq_main<<<NBLOCKS, 256, SMEM_BYTES>>>(x, emb, out);
    vq_loss_final<<<1, NBLOCKS>>>(out);
}